// round 12
// baseline (speedup 1.0000x reference)
#include <cuda_runtime.h>
#include <cstdint>

#define MAXC 10016
#define MAXE 2010048
#define EMB 32
#define NB 33   // buckets = 32 knees + 1

// Scratch (__device__ globals; no allocation allowed)
__device__ __align__(16) float2 d_hist[MAXC * NB];    // per (candidate,bucket): {sum a, count}
__device__ float d_p[EMB], d_q[EMB], d_p1[EMB];
__device__ float d_u[EMB];
__device__ __align__(16) float d_W[EMB * EMB];        // w_t2 @ w_u1_bot
__device__ float d_q1v[EMB];
__device__ float d_ts[64];                             // sorted global thresholds (+INF pad)
__device__ int   d_perm[EMB];
// Piecewise-linear output table: out = U + a*V per (candidate, bucket)
__device__ __align__(16) float2 d_UV[(size_t)MAXC * NB * EMB];   // 84.6 MB
__device__ __align__(16) float  d_knee[MAXC * EMB];              // f32 knees
// Candidate-sorted edge list
__device__ __align__(16) int2 d_elist[MAXE];          // {float_as_int(a), e}
__device__ int d_ccnt[MAXC];                           // edges per candidate
__device__ int d_coff[MAXC];                           // exclusive offsets
__device__ int d_woff[MAXC];                           // working cursors (scatter)

// ---------------------------------------------------------------------------
// Precompute folded weights + sorted global thresholds (tiny, 1 block)
// ---------------------------------------------------------------------------
__global__ void precompute_kernel(const float* __restrict__ w_v2h,
                                  const float* __restrict__ b_v2h,
                                  const float* __restrict__ w_t1,
                                  const float* __restrict__ b_t1,
                                  const float* __restrict__ w_t2,
                                  const float* __restrict__ b_t2,
                                  const float* __restrict__ w_u1,
                                  const float* __restrict__ b_u1)
{
    __shared__ float tarr[EMB];
    int tid = threadIdx.x;
    int m = tid >> 5, k = tid & 31;

    float w = 0.f;
    #pragma unroll
    for (int j = 0; j < EMB; j++)
        w += w_t2[m * EMB + j] * w_u1[(EMB + j) * EMB + k];
    d_W[m * EMB + k] = w;

    if (m == 0) {
        float u = 0.f;
        #pragma unroll
        for (int j = 0; j < EMB; j++)
            u += b_t2[j] * w_u1[(EMB + j) * EMB + k];
        d_u[k] = u;

        float p = 0.f, q = 0.f, p1 = 0.f, q1 = 0.f;
        #pragma unroll
        for (int i = 0; i < EMB; i++) {
            float v = w_v2h[i];
            float b = b_v2h[i];
            p  += v * w_t1[i * EMB + k];
            q  += b * w_t1[i * EMB + k];
            p1 += v * w_u1[i * EMB + k];
            q1 += b * w_u1[i * EMB + k];
        }
        float qe = q + b_t1[k];
        d_p[k]   = p;
        d_q[k]   = qe;
        d_p1[k]  = p1;
        d_q1v[k] = q1 + b_u1[k];
        float t = (p != 0.f) ? (-qe / p) : __int_as_float(0x7f800000);
        tarr[k] = t;
    }
    __syncthreads();

    if (tid < 32) {
        float t = tarr[tid];
        int r = 0;
        #pragma unroll
        for (int j = 0; j < 32; j++) {
            float tj = tarr[j];
            r += (tj < t) || (tj == t && j < tid);
        }
        d_ts[r] = t;
        d_perm[r] = tid;
    } else if (tid < 64) {
        d_ts[tid] = __int_as_float(0x7f800000);
    }
}

// ---------------------------------------------------------------------------
// Pass 1: 4 edges/thread, bucket via 6-step search, red.v2 {a,1} per edge
// ---------------------------------------------------------------------------
__global__ __launch_bounds__(256) void pass1_kernel(
    const float* __restrict__ edge_attr,
    const int* __restrict__ src,
    int E)
{
    __shared__ float ts[64];
    if (threadIdx.x < 64) ts[threadIdx.x] = d_ts[threadIdx.x];
    __syncthreads();

    int base = (blockIdx.x * blockDim.x + threadIdx.x) * 4;
    if (base >= E) return;

    float a4[4];
    int   c4[4];
    if (base + 4 <= E) {
        float4 aa = *(const float4*)(edge_attr + base);
        int4   cc = *(const int4*)(src + base);
        a4[0]=aa.x; a4[1]=aa.y; a4[2]=aa.z; a4[3]=aa.w;
        c4[0]=cc.x; c4[1]=cc.y; c4[2]=cc.z; c4[3]=cc.w;
    } else {
        #pragma unroll
        for (int i = 0; i < 4; i++) {
            int e = (base + i < E) ? (base + i) : (E - 1);
            a4[i] = edge_attr[e];
            c4[i] = src[e];
        }
    }

    int n = (base + 4 <= E) ? 4 : (E - base);
    #pragma unroll
    for (int i = 0; i < 4; i++) {
        int p = 0;
        #pragma unroll
        for (int s = 32; s >= 1; s >>= 1)
            if (ts[p + s - 1] < a4[i]) p += s;
        if (i < n) {
            float2* addr = d_hist + c4[i] * NB + p;
            asm volatile("red.global.add.v2.f32 [%0], {%1, %2};"
                         :: "l"(addr), "f"(a4[i]), "f"(1.0f) : "memory");
        }
    }
}

// ---------------------------------------------------------------------------
// Fused G + UV build: warp per candidate. (knees stored f32)
// ---------------------------------------------------------------------------
__global__ __launch_bounds__(256) void guv_kernel(
    const float* __restrict__ w_u2,
    const float* __restrict__ b_u2,
    int C)
{
    __shared__ float sW[EMB * EMB];
    __shared__ float sw2[EMB * EMB];
    __shared__ float su[EMB], sq1[EMB], sp[EMB], sq[EMB], sp1[EMB], sb[EMB];
    __shared__ int   sperm[EMB];
    __shared__ float sR[8][EMB];
    __shared__ float st[8][EMB];
    __shared__ float sG[8][EMB];
    __shared__ int   sjb[8][EMB];

    for (int i = threadIdx.x; i < EMB * EMB; i += blockDim.x) {
        sW[i]  = d_W[i];
        sw2[i] = w_u2[i];
    }
    if (threadIdx.x < EMB) {
        su[threadIdx.x]  = d_u[threadIdx.x];
        sq1[threadIdx.x] = d_q1v[threadIdx.x];
        sp[threadIdx.x]  = d_p[threadIdx.x];
        sq[threadIdx.x]  = d_q[threadIdx.x];
        sp1[threadIdx.x] = d_p1[threadIdx.x];
        sb[threadIdx.x]  = b_u2[threadIdx.x];
        sperm[threadIdx.x] = d_perm[threadIdx.x];
    }
    __syncthreads();

    int lane = threadIdx.x & 31;
    int wid  = threadIdx.x >> 5;
    int c = blockIdx.x * 8 + wid;
    if (c >= C) return;

    // ---- stage 1: G ----
    float2 h   = d_hist[c * NB + lane];
    float2 h32 = d_hist[c * NB + 32];

    float Ps = h.x, Pn = h.y;
    #pragma unroll
    for (int d = 1; d < 32; d <<= 1) {
        float xs = __shfl_up_sync(0xffffffffu, Ps, d);
        float xn = __shfl_up_sync(0xffffffffu, Pn, d);
        if (lane >= d) { Ps += xs; Pn += xn; }
    }
    float Ts = __shfl_sync(0xffffffffu, Ps, 31) + h32.x;
    float Tn = __shfl_sync(0xffffffffu, Pn, 31) + h32.y;

    {
        int k = sperm[lane];
        float p = sp[k], q = sq[k];
        float sumR;
        if (p > 0.f)      sumR = p * (Ts - Ps) + q * (Tn - Pn);
        else if (p < 0.f) sumR = p * Ps + q * Pn;
        else              sumR = Tn * fmaxf(q, 0.f);
        sR[wid][k] = sumR;
    }
    __syncwarp();

    float Gk = sq1[lane] + Tn * su[lane];
    #pragma unroll
    for (int m = 0; m < EMB; m++)
        Gk = fmaf(sR[wid][m], sW[m * EMB + lane], Gk);

    // ---- stage 2: knees ----
    float p1k = sp1[lane];
    float t = (p1k != 0.f) ? (-Gk / p1k) : __int_as_float(0x7f800000);
    d_knee[c * EMB + lane] = t;

    st[wid][lane] = t;
    sG[wid][lane] = Gk;
    __syncwarp();

    int r = 0;
    #pragma unroll
    for (int j = 0; j < EMB; j++) {
        float tj = st[wid][j];
        r += (tj < t) || (tj == t && j < lane);
    }
    sjb[wid][r] = lane;
    __syncwarp();

    // ---- stage 3: UV ----
    float U = sb[lane];
    float V = 0.f;
    #pragma unroll
    for (int j = 0; j < EMB; j++) {
        float pj = sp1[j];
        float gj = sG[wid][j];
        bool act = (pj < 0.f) || (pj == 0.f && gj > 0.f);
        if (act) {
            U = fmaf(gj, sw2[j * EMB + lane], U);
            V = fmaf(pj, sw2[j * EMB + lane], V);
        }
    }

    float2* uvrow = d_UV + (size_t)c * NB * EMB;
    uvrow[lane] = make_float2(U, V);

    for (int b = 1; b < NB; b++) {
        int j = sjb[wid][b - 1];
        float pj = sp1[j];
        float s = (pj > 0.f) ? 1.f : ((pj < 0.f) ? -1.f : 0.f);
        float wjk = sw2[j * EMB + lane];
        U = fmaf(s * sG[wid][j], wjk, U);
        V = fmaf(s * pj, wjk, V);
        uvrow[b * EMB + lane] = make_float2(U, V);
    }
}

// ---------------------------------------------------------------------------
// Per-candidate edge counts from hist (counts are exact small ints in f32)
// ---------------------------------------------------------------------------
__global__ __launch_bounds__(256) void countk_kernel(int C)
{
    int c = blockIdx.x * blockDim.x + threadIdx.x;
    if (c >= C) return;
    float s = 0.f;
    #pragma unroll
    for (int b = 0; b < NB; b++)
        s += d_hist[c * NB + b].y;
    d_ccnt[c] = (int)(s + 0.5f);
}

// ---------------------------------------------------------------------------
// Exclusive scan of counts (single block, 1024 threads, ~10 cands/thread)
// ---------------------------------------------------------------------------
__global__ __launch_bounds__(1024) void scank_kernel(int C)
{
    __shared__ int part[1024];
    int tid = threadIdx.x;
    int per = (C + 1023) / 1024;
    int base = tid * per;

    int s = 0;
    for (int i = 0; i < per; i++)
        if (base + i < C) s += d_ccnt[base + i];
    part[tid] = s;
    __syncthreads();

    // Hillis-Steele inclusive scan
    for (int d = 1; d < 1024; d <<= 1) {
        int v = (tid >= d) ? part[tid - d] : 0;
        __syncthreads();
        part[tid] += v;
        __syncthreads();
    }
    int ex = (tid == 0) ? 0 : part[tid - 1];

    int run = ex;
    for (int i = 0; i < per; i++) {
        if (base + i < C) {
            d_coff[base + i] = run;
            d_woff[base + i] = run;
            run += d_ccnt[base + i];
        }
    }
}

// ---------------------------------------------------------------------------
// Scatter: candidate-sorted edge list {a, e}
// ---------------------------------------------------------------------------
__global__ __launch_bounds__(256) void scatter_kernel(
    const float* __restrict__ edge_attr,
    const int* __restrict__ src,
    int E)
{
    int base = (blockIdx.x * blockDim.x + threadIdx.x) * 4;
    if (base >= E) return;

    float a4[4];
    int   c4[4];
    if (base + 4 <= E) {
        float4 aa = *(const float4*)(edge_attr + base);
        int4   cc = *(const int4*)(src + base);
        a4[0]=aa.x; a4[1]=aa.y; a4[2]=aa.z; a4[3]=aa.w;
        c4[0]=cc.x; c4[1]=cc.y; c4[2]=cc.z; c4[3]=cc.w;
    } else {
        #pragma unroll
        for (int i = 0; i < 4; i++) {
            int e = (base + i < E) ? (base + i) : (E - 1);
            a4[i] = edge_attr[e];
            c4[i] = src[e];
        }
    }

    int n = (base + 4 <= E) ? 4 : (E - base);
    #pragma unroll
    for (int i = 0; i < 4; i++) {
        if (i < n) {
            int pos = atomicAdd(&d_woff[c4[i]], 1);
            d_elist[pos] = make_int2(__float_as_int(a4[i]), base + i);
        }
    }
}

// ---------------------------------------------------------------------------
// Pass 2 (clustered): block loops over candidates. UV table in smem,
// knees in regs. Per edge: 2 shfl + ballot + 1 LDS.64 + fma + 128B store.
// ---------------------------------------------------------------------------
__global__ __launch_bounds__(256) void pass2_kernel(
    float* __restrict__ out,
    int C)
{
    __shared__ __align__(16) float2 suv[NB * EMB];   // 8448 B

    int tid  = threadIdx.x;
    int lane = tid & 31;
    int wid  = tid >> 5;

    for (int c = blockIdx.x; c < C; c += gridDim.x) {
        // load candidate's UV table into smem
        const float2* uvsrc = d_UV + (size_t)c * NB * EMB;
        for (int i = tid; i < NB * EMB; i += 256)
            suv[i] = uvsrc[i];
        float tl = d_knee[c * EMB + lane];   // knee for this lane's feature
        int off = d_coff[c];
        int cnt = d_ccnt[c];
        __syncthreads();

        for (int bse = wid * 16; bse < cnt; bse += 128) {
            int nb = min(16, cnt - bse);
            int2 el = make_int2(0, 0);
            if (lane < nb) el = d_elist[off + bse + lane];
            float al  = __int_as_float(el.x);
            int   eil = el.y;

            for (int j = 0; j < nb; j++) {
                float a = __shfl_sync(0xffffffffu, al, j);
                int   e = __shfl_sync(0xffffffffu, eil, j);
                int   b = __popc(__ballot_sync(0xffffffffu, tl < a));
                float2 uv = suv[b * EMB + lane];
                float o = fmaf(a, uv.y, uv.x);
                asm volatile("st.global.cs.f32 [%0], %1;"
                             :: "l"(out + (size_t)e * EMB + lane), "f"(o)
                             : "memory");
            }
        }
        __syncthreads();
    }
}

// ---------------------------------------------------------------------------
extern "C" void kernel_launch(void* const* d_in, const int* in_sizes, int n_in,
                              void* d_out, int out_size)
{
    const float* edge_attr  = (const float*)d_in[0];
    const int*   edge_index = (const int*)d_in[1];   // [2, E] int32; row 0 = src
    const float* w_v2h = (const float*)d_in[3];
    const float* b_v2h = (const float*)d_in[4];
    const float* w_t1  = (const float*)d_in[5];
    const float* b_t1  = (const float*)d_in[6];
    const float* w_t2  = (const float*)d_in[7];
    const float* b_t2  = (const float*)d_in[8];
    const float* w_u1  = (const float*)d_in[9];
    const float* b_u1  = (const float*)d_in[10];
    const float* w_u2  = (const float*)d_in[11];
    const float* b_u2  = (const float*)d_in[12];
    float*       out   = (float*)d_out;

    int E = in_sizes[0];
    int C = in_sizes[2];

    void* hist_ptr = nullptr;
    cudaGetSymbolAddress(&hist_ptr, d_hist);
    cudaMemsetAsync(hist_ptr, 0, (size_t)C * NB * sizeof(float2), 0);

    precompute_kernel<<<1, 1024, 0, 0>>>(w_v2h, b_v2h, w_t1, b_t1,
                                         w_t2, b_t2, w_u1, b_u1);

    int p1threads = (E + 3) / 4;
    int p1blocks = (p1threads + 255) / 256;
    pass1_kernel<<<p1blocks, 256, 0, 0>>>(edge_attr, edge_index, E);

    int gblocks = (C + 7) / 8;
    guv_kernel<<<gblocks, 256, 0, 0>>>(w_u2, b_u2, C);

    countk_kernel<<<(C + 255) / 256, 256, 0, 0>>>(C);
    scank_kernel<<<1, 1024, 0, 0>>>(C);
    scatter_kernel<<<p1blocks, 256, 0, 0>>>(edge_attr, edge_index, E);

    pass2_kernel<<<1252, 256, 0, 0>>>(out, C);
}